// round 1
// baseline (speedup 1.0000x reference)
#include <cuda_runtime.h>
#include <cstdint>

// Problem constants
#define Bb   8
#define Np   8192
#define Sp   2048
#define Kp   32
#define Dp   128
#define C0   131          // D + 3
#define M0   128
#define M1   128
#define M2   256
#define HIDp 8
#define LEAKYF 0.1f
#define FLATN (M2*HIDp)   // 2048

// Scratch (device globals: allocation-free rule)
__device__ float g_flat[(size_t)Bb * Sp * FLATN];   // 134 MB
__device__ float g_ptsT[(size_t)Bb * Np * Dp];      // 32 MB  [b][n][c]
__device__ int   g_knn[Bb * Sp * Kp];               // 2 MB

__device__ __forceinline__ float lrelu(float x) { return x > 0.0f ? x : LEAKYF * x; }

// ---------------------------------------------------------------------------
// Kernel 0: copy new_xyz = xyz[:, :, :S] to output head
// ---------------------------------------------------------------------------
__global__ void copy_newxyz_kernel(const float* __restrict__ xyz, float* __restrict__ out)
{
    int idx = blockIdx.x * blockDim.x + threadIdx.x;          // 0 .. B*3*S-1
    if (idx >= Bb * 3 * Sp) return;
    int b = idx / (3 * Sp);
    int r = idx - b * 3 * Sp;
    int c = r / Sp;
    int s = r - c * Sp;
    out[idx] = xyz[(b * 3 + c) * Np + s];
}

// ---------------------------------------------------------------------------
// Kernel 1: transpose points [B][D][N] -> ptsT [B][N][D]
// ---------------------------------------------------------------------------
__global__ void transpose_kernel(const float* __restrict__ p)
{
    __shared__ float tile[32][33];
    int b  = blockIdx.z;
    int nb = blockIdx.x * 32;     // n block
    int cb = blockIdx.y * 32;     // c block
    int tx = threadIdx.x;         // 0..31
    int ty = threadIdx.y;         // 0..7
    const float* src = p + (size_t)b * Dp * Np;
    float* dst = g_ptsT + (size_t)b * Np * Dp;
    #pragma unroll
    for (int j = ty; j < 32; j += 8)
        tile[j][tx] = src[(size_t)(cb + j) * Np + nb + tx];
    __syncthreads();
    #pragma unroll
    for (int j = ty; j < 32; j += 8)
        dst[(size_t)(nb + j) * Dp + cb + tx] = tile[tx][j];
}

// ---------------------------------------------------------------------------
// Kernel 2: KNN. One CTA (256 threads) per (b,s) query.
// Each thread holds 32 distances in registers (points n = tid + 256*i).
// 32 rounds: cross-CTA argmin with (dist, index) tie-break; winner thread
// masks its slot and rescans its registers.
// Encoding trick: global index n = tid + 256*slot, so the packed candidate id
// IS the point index, and (id & 255) is the owner thread.
// ---------------------------------------------------------------------------
__global__ void __launch_bounds__(256) knn_kernel(const float* __restrict__ xyz)
{
    const int bs = blockIdx.x;
    const int b  = bs >> 11;
    const int s  = bs & (Sp - 1);
    const float* X = xyz + (size_t)b * 3 * Np;
    const int t = threadIdx.x;

    const float qx = X[s], qy = X[Np + s], qz = X[2 * Np + s];
    const float qq = qx * qx + qy * qy + qz * qz;

    float d[32];
    #pragma unroll
    for (int i = 0; i < 32; i++) {
        int n = t + (i << 8);
        float px = X[n], py = X[Np + n], pz = X[2 * Np + n];
        float pp  = px * px + py * py + pz * pz;
        float dot = qx * px + qy * py + qz * pz;
        d[i] = (qq + pp) - 2.0f * dot;   // same formula as reference
    }

    float lbv = d[0]; int lbs = 0;
    #pragma unroll
    for (int i = 1; i < 32; i++) if (d[i] < lbv) { lbv = d[i]; lbs = i; }

    __shared__ float bv[256];
    __shared__ int   bi[256];
    __shared__ int   s_sel[Kp];
    __shared__ int   s_cur;

    for (int r = 0; r < Kp; r++) {
        bv[t] = lbv;
        bi[t] = t + (lbs << 8);     // == global point index
        __syncthreads();
        if (t < 32) {
            float v = bv[t]; int id = bi[t];
            #pragma unroll
            for (int j = 1; j < 8; j++) {
                float v2 = bv[t + 32 * j]; int i2 = bi[t + 32 * j];
                if (v2 < v || (v2 == v && i2 < id)) { v = v2; id = i2; }
            }
            #pragma unroll
            for (int off = 16; off > 0; off >>= 1) {
                float v2 = __shfl_down_sync(0xffffffffu, v, off);
                int   i2 = __shfl_down_sync(0xffffffffu, id, off);
                if (v2 < v || (v2 == v && i2 < id)) { v = v2; id = i2; }
            }
            if (t == 0) { s_sel[r] = id; s_cur = id; }
        }
        __syncthreads();
        int cid = s_cur;
        if ((cid & 255) == t) {
            int slot = cid >> 8;
            #pragma unroll
            for (int i = 0; i < 32; i++) if (i == slot) d[i] = 3.0e38f;
            lbv = d[0]; lbs = 0;
            #pragma unroll
            for (int i = 1; i < 32; i++) if (d[i] < lbv) { lbv = d[i]; lbs = i; }
        }
        // next round's bv/bi writes are safely ordered by the syncs above
    }
    if (t < Kp) g_knn[bs * Kp + t] = s_sel[t];
}

// ---------------------------------------------------------------------------
// Kernel 3: per-(b,s) MLP stack. 128 threads, one CTA per (b,s).
//   gather feats[32][131] -> weightnet w[32][8]
//   h1[32][128] -> h2[32][128] -> h3[32][256]
//   agg[256][8] -> g_flat
// Dynamic smem layout (floats):
//   sfeat [32*132] | sh1 [32*128] | sh2 [32*128] | sh3 [32*256] | swm [32*8] | sidx(int)[32]
// ---------------------------------------------------------------------------
#define SMEM_FLOATS (32*132 + 32*128 + 32*128 + 32*256 + 32*8)
#define SMEM_BYTES  (SMEM_FLOATS*4 + 32*4)

__global__ void __launch_bounds__(128) mlp_kernel(
    const float* __restrict__ xyz,
    const float* __restrict__ w1, const float* __restrict__ w2, const float* __restrict__ w3,
    const float* __restrict__ wn1, const float* __restrict__ wb1,
    const float* __restrict__ wn2, const float* __restrict__ wb2,
    const float* __restrict__ wn3, const float* __restrict__ wb3)
{
    extern __shared__ float sm[];
    float* sfeat = sm;                    // [32][132] (ch 0..2 dir, 3..130 pts)
    float* sh1   = sfeat + 32 * 132;      // [32][128]
    float* sh2   = sh1 + 32 * 128;        // [32][128]
    float* sh3   = sh2 + 32 * 128;        // [32][256]
    float* swm   = sh3 + 32 * 256;        // [32][8]
    int*   sidx  = (int*)(swm + 32 * 8);  // [32]

    const int bs = blockIdx.x;
    const int b  = bs >> 11;
    const int s  = bs & (Sp - 1);
    const int t  = threadIdx.x;
    const float* X  = xyz + (size_t)b * 3 * Np;
    const float* PT = g_ptsT + (size_t)b * Np * Dp;

    if (t < 32) sidx[t] = g_knn[bs * Kp + t];
    __syncthreads();

    const float qx = X[s], qy = X[Np + s], qz = X[2 * Np + s];

    // gather point features: per k, 128 contiguous floats
    #pragma unroll 4
    for (int k = 0; k < 32; k++) {
        int n = sidx[k];
        sfeat[k * 132 + 3 + t] = PT[(size_t)n * Dp + t];
    }
    // gather direction (32 k x 3 c = 96 elements)
    if (t < 96) {
        int k = t / 3, c = t - k * 3;
        int n = sidx[k];
        float v;
        if (c == 0)      v = X[n]          - qx;
        else if (c == 1) v = X[Np + n]     - qy;
        else             v = X[2 * Np + n] - qz;
        sfeat[k * 132 + c] = v;
    }
    __syncthreads();

    // weightnet (warp 0, one thread per k)
    if (t < 32) {
        float dx = sfeat[t * 132 + 0], dy = sfeat[t * 132 + 1], dz = sfeat[t * 132 + 2];
        float h[8], g[8];
        #pragma unroll
        for (int o = 0; o < 8; o++) {
            float a = wn1[o * 3 + 0] * dx + wn1[o * 3 + 1] * dy + wn1[o * 3 + 2] * dz + wb1[o];
            h[o] = a > 0.0f ? a : 0.0f;
        }
        #pragma unroll
        for (int o = 0; o < 8; o++) {
            float a = wb2[o];
            #pragma unroll
            for (int c = 0; c < 8; c++) a += wn2[o * 8 + c] * h[c];
            g[o] = a > 0.0f ? a : 0.0f;
        }
        #pragma unroll
        for (int o = 0; o < 8; o++) {
            float a = wb3[o];
            #pragma unroll
            for (int c = 0; c < 8; c++) a += wn3[o * 8 + c] * g[c];
            swm[t * 8 + o] = a > 0.0f ? a : 0.0f;
        }
    }

    // ---- layer 1: feats[32][131] @ w1[o=t][131] -> sh1[32][128]
    {
        const float* wr = w1 + t * C0;
        float acc[32];
        #pragma unroll
        for (int k = 0; k < 32; k++) acc[k] = 0.0f;
        #pragma unroll 4
        for (int c = 0; c < C0; c++) {
            float w = __ldg(wr + c);
            #pragma unroll
            for (int k = 0; k < 32; k++) acc[k] += w * sfeat[k * 132 + c];
        }
        #pragma unroll
        for (int k = 0; k < 32; k++) sh1[k * 128 + t] = lrelu(acc[k]);
    }
    __syncthreads();

    // ---- layer 2: sh1[32][128] @ w2[o=t][128] -> sh2[32][128]
    {
        const float* wr = w2 + t * M0;
        float acc[32];
        #pragma unroll
        for (int k = 0; k < 32; k++) acc[k] = 0.0f;
        #pragma unroll 4
        for (int c = 0; c < M0; c++) {
            float w = __ldg(wr + c);
            #pragma unroll
            for (int k = 0; k < 32; k++) acc[k] += w * sh1[k * 128 + c];
        }
        #pragma unroll
        for (int k = 0; k < 32; k++) sh2[k * 128 + t] = lrelu(acc[k]);
    }
    __syncthreads();

    // ---- layer 3: sh2[32][128] @ w3 -> sh3[32][256], 2 outputs per thread
    {
        const float* wr0 = w3 + (size_t)t * M1;
        const float* wr1 = w3 + (size_t)(t + 128) * M1;
        float a0[32], a1[32];
        #pragma unroll
        for (int k = 0; k < 32; k++) { a0[k] = 0.0f; a1[k] = 0.0f; }
        #pragma unroll 2
        for (int c = 0; c < M1; c++) {
            float wv0 = __ldg(wr0 + c);
            float wv1 = __ldg(wr1 + c);
            #pragma unroll
            for (int k = 0; k < 32; k++) {
                float f = sh2[k * 128 + c];
                a0[k] += wv0 * f;
                a1[k] += wv1 * f;
            }
        }
        #pragma unroll
        for (int k = 0; k < 32; k++) {
            sh3[k * 256 + t]       = lrelu(a0[k]);
            sh3[k * 256 + t + 128] = lrelu(a1[k]);
        }
    }
    __syncthreads();

    // ---- agg: agg[o][j] = sum_k h3[k][o]*w[k][j]; o = t and t+128
    {
        float ag0[8], ag1[8];
        #pragma unroll
        for (int j = 0; j < 8; j++) { ag0[j] = 0.0f; ag1[j] = 0.0f; }
        #pragma unroll 4
        for (int k = 0; k < 32; k++) {
            float h0 = sh3[k * 256 + t];
            float h1 = sh3[k * 256 + t + 128];
            #pragma unroll
            for (int j = 0; j < 8; j++) {
                float wv = swm[k * 8 + j];
                ag0[j] += h0 * wv;
                ag1[j] += h1 * wv;
            }
        }
        float* fo = g_flat + (size_t)bs * FLATN;
        float4* f4 = (float4*)(fo + t * 8);
        f4[0] = make_float4(ag0[0], ag0[1], ag0[2], ag0[3]);
        f4[1] = make_float4(ag0[4], ag0[5], ag0[6], ag0[7]);
        float4* g4 = (float4*)(fo + (t + 128) * 8);
        g4[0] = make_float4(ag1[0], ag1[1], ag1[2], ag1[3]);
        g4[1] = make_float4(ag1[4], ag1[5], ag1[6], ag1[7]);
    }
}

// ---------------------------------------------------------------------------
// Kernel 4: out = lrelu(flat[16384,2048] @ wlin[256,2048]^T), written as
// out[b][o][s].  Tiled GEMM: BM=64, BN=64, BK=16, 256 threads, 4x4 per thread.
// ---------------------------------------------------------------------------
#define BM 64
#define BN 64
#define BKk 16

__global__ void __launch_bounds__(256) out_gemm_kernel(
    const float* __restrict__ Wl, float* __restrict__ outp)
{
    __shared__ float As[BKk][BM];
    __shared__ float Bs[BKk][BN];

    const int bm = blockIdx.x;     // 0..255
    const int bn = blockIdx.y;     // 0..3
    const int t  = threadIdx.x;
    const int m0 = bm * BM, n0 = bn * BN;
    const int tx = t & 15, ty = t >> 4;       // 16 x 16
    const int lr = t >> 2;                    // 0..63
    const int lc = (t & 3) * 4;               // 0,4,8,12

    const float* A = g_flat;

    float acc[4][4];
    #pragma unroll
    for (int i = 0; i < 4; i++)
        #pragma unroll
        for (int j = 0; j < 4; j++) acc[i][j] = 0.0f;

    for (int k0 = 0; k0 < FLATN; k0 += BKk) {
        float4 a = *(const float4*)(A + (size_t)(m0 + lr) * FLATN + k0 + lc);
        As[lc + 0][lr] = a.x; As[lc + 1][lr] = a.y; As[lc + 2][lr] = a.z; As[lc + 3][lr] = a.w;
        float4 bq = *(const float4*)(Wl + (size_t)(n0 + lr) * FLATN + k0 + lc);
        Bs[lc + 0][lr] = bq.x; Bs[lc + 1][lr] = bq.y; Bs[lc + 2][lr] = bq.z; Bs[lc + 3][lr] = bq.w;
        __syncthreads();
        #pragma unroll
        for (int k = 0; k < BKk; k++) {
            float4 av = *(const float4*)&As[k][ty * 4];
            float4 bv = *(const float4*)&Bs[k][tx * 4];
            float aa[4] = {av.x, av.y, av.z, av.w};
            float bb[4] = {bv.x, bv.y, bv.z, bv.w};
            #pragma unroll
            for (int i = 0; i < 4; i++)
                #pragma unroll
                for (int j = 0; j < 4; j++)
                    acc[i][j] += aa[i] * bb[j];
        }
        __syncthreads();
    }

    #pragma unroll
    for (int i = 0; i < 4; i++) {
        int mm = m0 + ty * 4 + i;
        int bb = mm >> 11, ss = mm & (Sp - 1);
        float* ob = outp + (size_t)bb * M2 * Sp + ss;
        #pragma unroll
        for (int j = 0; j < 4; j++) {
            ob[(size_t)(n0 + tx * 4 + j) * Sp] = lrelu(acc[i][j]);
        }
    }
}

// ---------------------------------------------------------------------------
// Launcher
// ---------------------------------------------------------------------------
extern "C" void kernel_launch(void* const* d_in, const int* in_sizes, int n_in,
                              void* d_out, int out_size)
{
    const float* xyz  = (const float*)d_in[0];
    const float* pts  = (const float*)d_in[1];
    const float* w1   = (const float*)d_in[2];
    const float* w2   = (const float*)d_in[3];
    const float* w3   = (const float*)d_in[4];
    const float* wn1  = (const float*)d_in[5];
    const float* wb1  = (const float*)d_in[6];
    const float* wn2  = (const float*)d_in[7];
    const float* wb2  = (const float*)d_in[8];
    const float* wn3  = (const float*)d_in[9];
    const float* wb3  = (const float*)d_in[10];
    const float* wlin = (const float*)d_in[11];
    float* out = (float*)d_out;

    // new_xyz copy (B*3*S = 49152 floats)
    copy_newxyz_kernel<<<(Bb * 3 * Sp + 255) / 256, 256>>>(xyz, out);

    // transpose points -> [B][N][D]
    {
        dim3 g(Np / 32, Dp / 32, Bb);
        dim3 blk(32, 8);
        transpose_kernel<<<g, blk>>>(pts);
    }

    // KNN
    knn_kernel<<<Bb * Sp, 256>>>(xyz);

    // MLP stack
    cudaFuncSetAttribute(mlp_kernel, cudaFuncAttributeMaxDynamicSharedMemorySize, SMEM_BYTES);
    mlp_kernel<<<Bb * Sp, 128, SMEM_BYTES>>>(xyz, w1, w2, w3,
                                             wn1, wb1, wn2, wb2, wn3, wb3);

    // final linear -> out[b][o][s] at offset B*3*S
    {
        dim3 g((Bb * Sp) / BM, M2 / BN);
        out_gemm_kernel<<<g, 256>>>(wlin, out + Bb * 3 * Sp);
    }
}